// round 2
// baseline (speedup 1.0000x reference)
#include <cuda_runtime.h>
#include <cstdint>

// Problem geometry
#define CDIM 512
#define KDIM 65536
#define TILE 64
#define KT   16
#define SPLITK 16
#define KSLICE (KDIM / SPLITK)          // 4096
#define NT   (CDIM / TILE)              // 8
#define NPAIRS (NT * (NT + 1) / 2)      // 36
#define SPAD 4                          // smem row pad: stride 68 floats (16B-aligned LDS.128)

typedef unsigned long long u64;

// Deterministic split-K scratch (no device allocation allowed -> __device__ global)
__device__ float g_scratch[(size_t)SPLITK * CDIM * CDIM];

__device__ __forceinline__ u64 pk2(float lo, float hi) {
    u64 r;
    asm("mov.b64 %0, {%1, %2};" : "=l"(r) : "f"(lo), "f"(hi));
    return r;
}

__device__ __forceinline__ void fma2(u64& d, u64 a, u64 b) {
    // Packed 2-wide fp32 FMA (Blackwell FFMA2) - 2 FLOPs/lane/issue on the fma pipe.
    asm("fma.rn.f32x2 %0, %1, %2, %0;" : "+l"(d) : "l"(a), "l"(b));
}

__global__ __launch_bounds__(256, 2) void gram_partial(const float* __restrict__ X) {
    __shared__ float As[KT][TILE + SPAD];
    __shared__ float Bs[KT][TILE + SPAD];

    const int p     = blockIdx.x;   // lower-triangle tile-pair index
    const int split = blockIdx.y;   // split-K slice

    // decode p -> (bi, bj), bi >= bj
    int bi = 0;
    while ((bi + 1) * (bi + 2) / 2 <= p) bi++;
    const int bj = p - bi * (bi + 1) / 2;

    const int tid = threadIdx.x;
    const int ty  = tid >> 4;       // 0..15 (row group)
    const int tx  = tid & 15;       // 0..15 (col group)

    // loader mapping: 64 rows x 4 float4-segments
    const int lr = tid >> 2;        // 0..63 row within tile
    const int ls = tid & 3;         // 0..3 segment

    const float* Aptr = X + (size_t)(bi * TILE + lr) * KDIM + (size_t)split * KSLICE + ls * 4;
    const float* Bptr = X + (size_t)(bj * TILE + lr) * KDIM + (size_t)split * KSLICE + ls * 4;

    u64 acc[4][2];
    #pragma unroll
    for (int i = 0; i < 4; i++) {
        acc[i][0] = pk2(0.f, 0.f);
        acc[i][1] = pk2(0.f, 0.f);
    }

    const bool diag = (bi == bj);

    for (int k0 = 0; k0 < KSLICE; k0 += KT) {
        float4 a = *(const float4*)(Aptr + k0);
        float4 b;
        if (!diag) b = *(const float4*)(Bptr + k0);
        else       b = a;

        // K-transposed stores so compute phase reads contiguous rows via LDS.128
        As[ls * 4 + 0][lr] = a.x;
        As[ls * 4 + 1][lr] = a.y;
        As[ls * 4 + 2][lr] = a.z;
        As[ls * 4 + 3][lr] = a.w;
        Bs[ls * 4 + 0][lr] = b.x;
        Bs[ls * 4 + 1][lr] = b.y;
        Bs[ls * 4 + 2][lr] = b.z;
        Bs[ls * 4 + 3][lr] = b.w;
        __syncthreads();

        #pragma unroll
        for (int kk = 0; kk < KT; kk++) {
            float4 av = *(const float4*)(&As[kk][ty * 4]);
            float4 bv = *(const float4*)(&Bs[kk][tx * 4]);
            u64 b0 = pk2(bv.x, bv.y);
            u64 b1 = pk2(bv.z, bv.w);
            u64 a0 = pk2(av.x, av.x);
            u64 a1 = pk2(av.y, av.y);
            u64 a2 = pk2(av.z, av.z);
            u64 a3 = pk2(av.w, av.w);
            fma2(acc[0][0], a0, b0); fma2(acc[0][1], a0, b1);
            fma2(acc[1][0], a1, b0); fma2(acc[1][1], a1, b1);
            fma2(acc[2][0], a2, b0); fma2(acc[2][1], a2, b1);
            fma2(acc[3][0], a3, b0); fma2(acc[3][1], a3, b1);
        }
        __syncthreads();
    }

    float* out = g_scratch + (size_t)split * CDIM * CDIM;
    const int gi0 = bi * TILE + ty * 4;
    const int gj0 = bj * TILE + tx * 4;
    #pragma unroll
    for (int i = 0; i < 4; i++) {
        // unpack f32x2 pairs: acc[i] = cols {gj0, gj0+1, gj0+2, gj0+3}
        float2 lo = *(float2*)&acc[i][0];
        float2 hi = *(float2*)&acc[i][1];
        float4 v = make_float4(lo.x, lo.y, hi.x, hi.y);
        *(float4*)(out + (size_t)(gi0 + i) * CDIM + gj0) = v;
    }
}

__global__ void gram_reduce(float* __restrict__ out) {
    const int idx = blockIdx.x * blockDim.x + threadIdx.x;
    if (idx >= CDIM * CDIM) return;
    const int i = idx / CDIM;
    const int j = idx % CDIM;
    if (j > i) return;          // mirror handles upper triangle
    float s = 0.f;
    #pragma unroll
    for (int sp = 0; sp < SPLITK; sp++)
        s += g_scratch[(size_t)sp * CDIM * CDIM + idx];
    out[(size_t)i * CDIM + j] = s;
    out[(size_t)j * CDIM + i] = s;
}

extern "C" void kernel_launch(void* const* d_in, const int* in_sizes, int n_in,
                              void* d_out, int out_size) {
    const float* x = (const float*)d_in[0];     // [1,512,256,256] contiguous = [512, 65536]
    float* out = (float*)d_out;                 // [1,1,512,512]

    dim3 grid(NPAIRS, SPLITK);
    gram_partial<<<grid, 256>>>(x);
    gram_reduce<<<(CDIM * CDIM + 255) / 256, 256>>>(out);
}

// round 4
// speedup vs baseline: 4.1464x; 4.1464x over previous
#include <cuda_runtime.h>
#include <cstdint>

#define CD 512
#define KD 65536
#define BM 128
#define BK 32
#define NT 4                         // 512/128
#define NPAIRS 10                    // NT*(NT+1)/2
#define SPLITS 29
#define NCHUNK (KD / BK)             // 2048
#define NSTAGE 3
#define ASTRIDE 36                   // floats per smem row (bank-conflict-free)
#define TILE_FLOATS (BM * ASTRIDE)   // one 128x32 tile (padded)
#define STAGE_FLOATS (2 * TILE_FLOATS)
#define SMEM_BYTES (NSTAGE * STAGE_FLOATS * 4)

// Deterministic split-K scratch (no device allocation allowed)
__device__ float g_scratch[(size_t)SPLITS * CD * CD];

__device__ __forceinline__ uint32_t s2u(const void* p) {
    uint32_t a;
    asm("{ .reg .u64 t; cvta.to.shared.u64 t, %1; cvt.u32.u64 %0, t; }" : "=r"(a) : "l"(p));
    return a;
}

__device__ __forceinline__ uint32_t cvt_tf32(float x) {
    uint32_t r;
    asm("cvt.rna.tf32.f32 %0, %1;" : "=r"(r) : "f"(x));
    return r;
}

__device__ __forceinline__ void cp16(uint32_t dst, const float* src) {
    asm volatile("cp.async.cg.shared.global [%0], [%1], 16;" :: "r"(dst), "l"(src) : "memory");
}

__global__ __launch_bounds__(128, 2) void gram_mma(const float* __restrict__ X) {
    extern __shared__ float smem[];
    const uint32_t sb = s2u(smem);

    const int pair  = blockIdx.x % NPAIRS;
    const int split = blockIdx.x / NPAIRS;

    int bi = 0;
    while ((bi + 1) * (bi + 2) / 2 <= pair) bi++;
    const int bj = pair - bi * (bi + 1) / 2;

    const int c0 = (split * NCHUNK) / SPLITS;
    const int c1 = ((split + 1) * NCHUNK) / SPLITS;

    const int tid  = threadIdx.x;
    const int lane = tid & 31;
    const int wid  = tid >> 5;
    const int wr   = wid >> 1;          // warp row (0..1) -> rows 64*wr
    const int wc   = wid & 1;           // warp col (0..1) -> cols 64*wc
    const int g    = lane >> 2;         // group id 0..7
    const int t    = lane & 3;          // thread-in-group 0..3

    // loader mapping: per tile 128 rows x 8 segs(16B); thread does rows ldr+16*k, seg lds
    const int ldr = tid >> 3;           // 0..15
    const int lds_ = tid & 7;           // 0..7
    const float* gA = X + (size_t)(bi * BM + ldr) * KD + lds_ * 4;
    const float* gB = X + (size_t)(bj * BM + ldr) * KD + lds_ * 4;

    float acc[4][8][4];
    #pragma unroll
    for (int mi = 0; mi < 4; mi++)
        #pragma unroll
        for (int ni = 0; ni < 8; ni++)
            #pragma unroll
            for (int e = 0; e < 4; e++) acc[mi][ni][e] = 0.f;

    const int niters = c1 - c0;

    // ---- prologue: issue stages 0..NSTAGE-2 ----
    #pragma unroll
    for (int s = 0; s < NSTAGE - 1; s++) {
        if (s < niters) {
            const int c = c0 + s;
            const uint32_t base = sb + (uint32_t)(s * STAGE_FLOATS) * 4u;
            #pragma unroll
            for (int r8 = 0; r8 < 8; r8++) {
                const int row = ldr + r8 * 16;
                uint32_t doff = (uint32_t)(row * ASTRIDE + lds_ * 4) * 4u;
                cp16(base + doff, gA + (size_t)(r8 * 16) * KD + (size_t)c * BK);
                cp16(base + (uint32_t)(TILE_FLOATS * 4) + doff,
                     gB + (size_t)(r8 * 16) * KD + (size_t)c * BK);
            }
        }
        asm volatile("cp.async.commit_group;" ::: "memory");
    }

    for (int i = 0; i < niters; i++) {
        asm volatile("cp.async.wait_group %0;" :: "n"(NSTAGE - 2) : "memory");
        __syncthreads();

        // issue stage i+NSTAGE-1
        {
            const int cn = c0 + i + NSTAGE - 1;
            if (cn < c1) {
                const int st = (i + NSTAGE - 1) % NSTAGE;
                const uint32_t base = sb + (uint32_t)(st * STAGE_FLOATS) * 4u;
                #pragma unroll
                for (int r8 = 0; r8 < 8; r8++) {
                    const int row = ldr + r8 * 16;
                    uint32_t doff = (uint32_t)(row * ASTRIDE + lds_ * 4) * 4u;
                    cp16(base + doff, gA + (size_t)(r8 * 16) * KD + (size_t)cn * BK);
                    cp16(base + (uint32_t)(TILE_FLOATS * 4) + doff,
                         gB + (size_t)(r8 * 16) * KD + (size_t)cn * BK);
                }
            }
            asm volatile("cp.async.commit_group;" ::: "memory");
        }

        // compute stage i%NSTAGE
        const float* As = smem + (i % NSTAGE) * STAGE_FLOATS;
        const float* Bs = As + TILE_FLOATS;

        #pragma unroll
        for (int kk = 0; kk < 4; kk++) {
            const int kc = kk * 8 + t;
            uint32_t ar[4][4];
            #pragma unroll
            for (int mi = 0; mi < 4; mi++) {
                const int r = 64 * wr + 16 * mi + g;
                ar[mi][0] = cvt_tf32(As[r * ASTRIDE + kc]);
                ar[mi][1] = cvt_tf32(As[(r + 8) * ASTRIDE + kc]);
                ar[mi][2] = cvt_tf32(As[r * ASTRIDE + kc + 4]);
                ar[mi][3] = cvt_tf32(As[(r + 8) * ASTRIDE + kc + 4]);
            }
            uint32_t br[8][2];
            #pragma unroll
            for (int ni = 0; ni < 8; ni++) {
                const int n = 64 * wc + 8 * ni + g;
                br[ni][0] = cvt_tf32(Bs[n * ASTRIDE + kc]);
                br[ni][1] = cvt_tf32(Bs[n * ASTRIDE + kc + 4]);
            }
            #pragma unroll
            for (int mi = 0; mi < 4; mi++)
                #pragma unroll
                for (int ni = 0; ni < 8; ni++) {
                    asm volatile(
                        "mma.sync.aligned.m16n8k8.row.col.f32.tf32.tf32.f32 "
                        "{%0,%1,%2,%3}, {%4,%5,%6,%7}, {%8,%9}, {%0,%1,%2,%3};"
                        : "+f"(acc[mi][ni][0]), "+f"(acc[mi][ni][1]),
                          "+f"(acc[mi][ni][2]), "+f"(acc[mi][ni][3])
                        : "r"(ar[mi][0]), "r"(ar[mi][1]), "r"(ar[mi][2]), "r"(ar[mi][3]),
                          "r"(br[ni][0]), "r"(br[ni][1]));
                }
        }
    }

    // epilogue: write 128x128 fp32 partial tile to scratch
    float* out = g_scratch + (size_t)split * CD * CD;
    #pragma unroll
    for (int mi = 0; mi < 4; mi++) {
        const int gi = bi * BM + 64 * wr + 16 * mi + g;
        #pragma unroll
        for (int ni = 0; ni < 8; ni++) {
            const int gj = bj * BM + 64 * wc + 8 * ni + 2 * t;
            *(float2*)(out + (size_t)gi * CD + gj)       = make_float2(acc[mi][ni][0], acc[mi][ni][1]);
            *(float2*)(out + (size_t)(gi + 8) * CD + gj) = make_float2(acc[mi][ni][2], acc[mi][ni][3]);
        }
    }
}

__global__ void gram_reduce(float* __restrict__ out) {
    const int idx = blockIdx.x * blockDim.x + threadIdx.x;
    const int i = idx >> 9;
    const int j = idx & 511;
    if (j > i) return;
    float s = 0.f;
    #pragma unroll 8
    for (int sp = 0; sp < SPLITS; ++sp)
        s += g_scratch[(size_t)sp * CD * CD + idx];
    out[(size_t)i * CD + j] = s;
    out[(size_t)j * CD + i] = s;
}

extern "C" void kernel_launch(void* const* d_in, const int* in_sizes, int n_in,
                              void* d_out, int out_size) {
    const float* x = (const float*)d_in[0];   // [1,512,256,256] = [512, 65536]
    float* out = (float*)d_out;               // [1,1,512,512]

    cudaFuncSetAttribute(gram_mma, cudaFuncAttributeMaxDynamicSharedMemorySize, SMEM_BYTES);
    gram_mma<<<NPAIRS * SPLITS, 128, SMEM_BYTES>>>(x);
    gram_reduce<<<(CD * CD) / 256, 256>>>(out);
}